// round 2
// baseline (speedup 1.0000x reference)
#include <cuda_runtime.h>
#include <math.h>

#define Bdim 8
#define Ndim 325
#define Tdim 24
#define Ddim 64
#define Hh   8
#define Mm   16
#define E2d  128

// ---------------- scratch (device globals; no runtime allocation) ----------------
__device__ float g_tfeat[Bdim * Mm];                                   // (B,16)
__device__ float g_gcn[(size_t)Bdim * Ndim * Tdim * Ddim];             // 16 MB
__device__ float g_W[(size_t)3 * Bdim * Ndim * E2d * E2d];             // 511 MB
__device__ float g_qkv[(size_t)3 * Bdim * Ndim * Tdim * E2d];          // 96 MB

__device__ __forceinline__ float lrelu(float x) { return x >= 0.f ? x : 0.1f * x; }

// ============================================================================
// K0: tfeat[b,m] = tanh( mean_t(tXin[b,0,t,:]) @ tproj_w + tproj_b )
// ============================================================================
__global__ void k_tfeat(const float* __restrict__ tXin,
                        const float* __restrict__ tproj_w,
                        const float* __restrict__ tproj_b) {
    __shared__ float s_mean[Bdim * Ddim];
    int tid = threadIdx.x;
    if (tid < Bdim * Ddim) {
        int b = tid >> 6, d = tid & 63;
        float s = 0.f;
        #pragma unroll
        for (int t = 0; t < Tdim; ++t)
            s += tXin[((size_t)(b * Ndim) * Tdim + t) * Ddim + d];
        s_mean[tid] = s * (1.0f / Tdim);
    }
    __syncthreads();
    if (tid < Bdim * Mm) {
        int b = tid >> 4, m = tid & 15;
        float a = tproj_b[m];
        #pragma unroll
        for (int d = 0; d < Ddim; ++d)
            a += s_mean[b * Ddim + d] * tproj_w[d * Mm + m];
        g_tfeat[tid] = tanhf(a);
    }
}

// ============================================================================
// K1: support[b,n,t,d] = sum_m matrix[b,t,n,m] * hidden[b,m,t,d]
//     gcn_out = relu(support @ gcn_w + gcn_b)   (fused epilogue)
// grid (ceil(N/64), T, B), block 256
// ============================================================================
__global__ void k_support_gcn(const float* __restrict__ matrix,
                              const float* __restrict__ hidden,
                              const float* __restrict__ gcn_w,
                              const float* __restrict__ gcn_b) {
    __shared__ float smem[8448];              // 33.8 KB
    float* s_hid = smem;                      // [32][64]
    float* s_mat = smem + 2048;               // [64][33]
    const int tid = threadIdx.x;
    const int n0 = blockIdx.x * 64;
    const int t  = blockIdx.y;
    const int b  = blockIdx.z;
    const int tx = tid & 15;                  // d-quad
    const int ty = tid >> 4;                  // row slot 0..15
    float4 acc[4];
    #pragma unroll
    for (int j = 0; j < 4; ++j) acc[j] = make_float4(0.f, 0.f, 0.f, 0.f);

    for (int mc = 0; mc < 11; ++mc) {
        const int m0 = mc * 32;
        for (int idx = tid; idx < 2048; idx += 256) {
            int mm = idx >> 6, d = idx & 63;
            int m = m0 + mm;
            s_hid[idx] = (m < Ndim) ? hidden[((size_t)(b * Ndim + m) * Tdim + t) * Ddim + d] : 0.f;
        }
        for (int idx = tid; idx < 2048; idx += 256) {
            int r = idx >> 5, mm = idx & 31;
            int n = n0 + r, m = m0 + mm;
            s_mat[r * 33 + mm] = (n < Ndim && m < Ndim)
                ? matrix[((size_t)(b * Tdim + t) * Ndim + n) * Ndim + m] : 0.f;
        }
        __syncthreads();
        #pragma unroll 8
        for (int mm = 0; mm < 32; ++mm) {
            float4 h4 = *(const float4*)&s_hid[mm * 64 + tx * 4];
            #pragma unroll
            for (int j = 0; j < 4; ++j) {
                float mv = s_mat[(ty + 16 * j) * 33 + mm];
                acc[j].x += mv * h4.x; acc[j].y += mv * h4.y;
                acc[j].z += mv * h4.z; acc[j].w += mv * h4.w;
            }
        }
        __syncthreads();
    }

    // ---- stage 2: gcn ----
    float* s_sup = smem;                      // [64][68]
    float* s_gw  = smem + 4352;               // [64][64]
    #pragma unroll
    for (int j = 0; j < 4; ++j)
        *(float4*)&s_sup[(ty + 16 * j) * 68 + tx * 4] = acc[j];
    for (int idx = tid; idx < 4096; idx += 256) s_gw[idx] = gcn_w[idx];
    __syncthreads();

    for (int task = tid; task < 1024; task += 256) {
        int r = task >> 4, e4 = task & 15;
        int n = n0 + r;
        if (n >= Ndim) continue;
        float4 a = *(const float4*)&gcn_b[e4 * 4];
        #pragma unroll 4
        for (int d = 0; d < 64; ++d) {
            float sv = s_sup[r * 68 + d];
            float4 g = *(const float4*)&s_gw[d * 64 + e4 * 4];
            a.x += sv * g.x; a.y += sv * g.y; a.z += sv * g.z; a.w += sv * g.w;
        }
        a.x = fmaxf(a.x, 0.f); a.y = fmaxf(a.y, 0.f);
        a.z = fmaxf(a.z, 0.f); a.w = fmaxf(a.w, 0.f);
        *(float4*)&g_gcn[((size_t)(b * Ndim + n) * Tdim + t) * Ddim + e4 * 4] = a;
    }
}

// ============================================================================
// K2: materialize W[mat,b,n,i,k] = sum_m node_emb[n,m]*tfeat[b,m]*Wmat[m,i,k]
// grid (16, B, 3), block 256. Each thread: fixed (i, k-quad), sweeps all n.
// Each WQ/WK/WV element is read exactly once per b from HBM/L2.
// ============================================================================
__global__ void k_buildW(const float* __restrict__ wq,
                         const float* __restrict__ wk,
                         const float* __restrict__ wv,
                         const float* __restrict__ node_emb) {
    __shared__ float s_ne[Ndim * Mm];         // 5200 floats = 20.8 KB
    const int tid  = threadIdx.x;
    const int k4   = tid & 31;
    const int iloc = tid >> 5;
    const int i    = blockIdx.x * 8 + iloc;
    const int b    = blockIdx.y;
    const int mat  = blockIdx.z;
    const float* Wsel = (mat == 0) ? wq : (mat == 1) ? wk : wv;

    for (int idx = tid; idx < Ndim * Mm; idx += 256) s_ne[idx] = node_emb[idx];

    float4 v[16];
    #pragma unroll
    for (int m = 0; m < 16; ++m) {
        float4 w = *(const float4*)&Wsel[(size_t)m * 16384 + i * 128 + k4 * 4];
        float tf = g_tfeat[b * 16 + m];
        v[m] = make_float4(w.x * tf, w.y * tf, w.z * tf, w.w * tf);
    }
    __syncthreads();

    float* outp = &g_W[((size_t)(mat * Bdim + b) * Ndim) * 16384 + i * 128 + k4 * 4];
    for (int n = 0; n < Ndim; ++n) {
        float4 o = make_float4(0.f, 0.f, 0.f, 0.f);
        const float* ne = &s_ne[n * 16];
        #pragma unroll
        for (int m = 0; m < 16; ++m) {
            float c = ne[m];
            o.x += c * v[m].x; o.y += c * v[m].y;
            o.z += c * v[m].z; o.w += c * v[m].w;
        }
        *(float4*)(outp + (size_t)n * 16384) = o;
    }
}

// ============================================================================
// K3: q/k/v[b,n,t,k] = lrelu( sum_i qkv[b,n,t,i] * W[mat,b,n,i,k] )
// qkv = concat(hidden, tXin) along i. grid (N, B, 3), block 256.
// ============================================================================
__global__ void k_qkvproj(const float* __restrict__ hidden,
                          const float* __restrict__ tXin) {
    __shared__ float s_x[Tdim * E2d];         // 3072 floats = 12 KB
    const int tid = threadIdx.x;
    const int n = blockIdx.x, b = blockIdx.y, mat = blockIdx.z;

    for (int idx = tid; idx < Tdim * E2d; idx += 256) {
        int t = idx >> 7, i = idx & 127;
        s_x[idx] = (i < 64)
            ? hidden[((size_t)(b * Ndim + n) * Tdim + t) * Ddim + i]
            : tXin  [((size_t)(b * Ndim + n) * Tdim + t) * Ddim + (i - 64)];
    }
    __syncthreads();

    const int k4 = tid & 31, slot = tid >> 5;
    const int t0 = slot * 3;
    const float* wp = &g_W[((size_t)(mat * Bdim + b) * Ndim + n) * 16384 + k4 * 4];
    float4 a0 = make_float4(0.f,0.f,0.f,0.f), a1 = a0, a2 = a0;
    #pragma unroll 4
    for (int i = 0; i < 128; ++i) {
        float4 w = *(const float4*)(wp + (size_t)i * 128);
        float x0 = s_x[t0 * 128 + i];
        float x1 = s_x[(t0 + 1) * 128 + i];
        float x2 = s_x[(t0 + 2) * 128 + i];
        a0.x += x0 * w.x; a0.y += x0 * w.y; a0.z += x0 * w.z; a0.w += x0 * w.w;
        a1.x += x1 * w.x; a1.y += x1 * w.y; a1.z += x1 * w.z; a1.w += x1 * w.w;
        a2.x += x2 * w.x; a2.y += x2 * w.y; a2.z += x2 * w.z; a2.w += x2 * w.w;
    }
    const size_t qbase = ((size_t)mat * (Bdim * Ndim) * Tdim + (size_t)(b * Ndim + n) * Tdim) * E2d;
    float4 r;
    r = make_float4(lrelu(a0.x), lrelu(a0.y), lrelu(a0.z), lrelu(a0.w));
    *(float4*)&g_qkv[qbase + (size_t)t0 * 128 + k4 * 4] = r;
    r = make_float4(lrelu(a1.x), lrelu(a1.y), lrelu(a1.z), lrelu(a1.w));
    *(float4*)&g_qkv[qbase + (size_t)(t0 + 1) * 128 + k4 * 4] = r;
    r = make_float4(lrelu(a2.x), lrelu(a2.y), lrelu(a2.z), lrelu(a2.w));
    *(float4*)&g_qkv[qbase + (size_t)(t0 + 2) * 128 + k4 * 4] = r;
}

// ============================================================================
// K4: per-(b,n): causal attention + out-proj + gate + residual
// grid (N, B), block 256, STATIC smem 43 KB (no cudaFuncSetAttribute needed)
// ============================================================================
__global__ void k_attn(const float* __restrict__ hidden,
                       const float* __restrict__ out_w,
                       const float* __restrict__ out_b,
                       const float* __restrict__ gate_w,
                       const float* __restrict__ gate_b,
                       float* __restrict__ out) {
    __shared__ float sm[10752];         // 43008 bytes
    float* s_k    = sm;                 // 3072 (later: val 24x128)
    float* s_v    = sm + 3072;          // 3072 (later: gcn 24x64)
    float* s_attn = sm + 6144;          // 4608 (later: value 24x64)
    const int tid = threadIdx.x;
    const int n = blockIdx.x, b = blockIdx.y;
    const size_t qstride = (size_t)Bdim * Ndim * Tdim * E2d;
    const size_t base    = (size_t)(b * Ndim + n) * Tdim * E2d;

    for (int idx = tid; idx < Tdim * E2d; idx += 256) {
        s_k[idx] = g_qkv[qstride + base + idx];
        s_v[idx] = g_qkv[2 * qstride + base + idx];
    }
    __syncthreads();

    // ---- scores + causal softmax: one thread per (t,h); q straight from global ----
    if (tid < 192) {
        int t = tid >> 3, h = tid & 7;
        float qreg[16];
        #pragma unroll
        for (int e = 0; e < 16; ++e) qreg[e] = g_qkv[base + t * 128 + h * 16 + e];
        float* arow = &s_attn[(h * 24 + t) * 24];
        float mx = -1e30f;
        for (int s = 0; s <= t; ++s) {
            float d = 0.f;
            #pragma unroll
            for (int e = 0; e < 16; ++e) d += qreg[e] * s_k[s * 128 + h * 16 + e];
            d *= 0.25f;                          // 1/sqrt(16)
            arow[s] = d;
            mx = fmaxf(mx, d);
        }
        float sum = 0.f;
        for (int s = 0; s <= t; ++s) { float e_ = expf(arow[s] - mx); arow[s] = e_; sum += e_; }
        float inv = 1.f / sum;
        for (int s = 0; s < 24; ++s) arow[s] = (s <= t) ? arow[s] * inv : 0.f;
    }
    __syncthreads();

    // ---- val[t,k] = sum_s attn[h,t,s]*v[s,k]  (h = k/16); write into s_k region ----
    {
        const int k4 = tid & 31, slot = tid >> 5;
        const int h = k4 >> 2;
        float4 acc[3];
        #pragma unroll
        for (int j = 0; j < 3; ++j) acc[j] = make_float4(0.f, 0.f, 0.f, 0.f);
        for (int s = 0; s < 24; ++s) {
            float4 v4 = *(const float4*)&s_v[s * 128 + k4 * 4];
            #pragma unroll
            for (int j = 0; j < 3; ++j) {
                float a = s_attn[(h * 24 + (slot * 3 + j)) * 24 + s];
                acc[j].x += a * v4.x; acc[j].y += a * v4.y;
                acc[j].z += a * v4.z; acc[j].w += a * v4.w;
            }
        }
        __syncthreads();   // everyone done reading s_k (as k) before overwrite
        #pragma unroll
        for (int j = 0; j < 3; ++j)
            *(float4*)&s_k[(slot * 3 + j) * 128 + k4 * 4] = acc[j];
    }
    __syncthreads();

    float* s_val   = s_k;               // 24x128
    float* s_gcn   = s_v;               // 24x64 (overwrites dead v)
    float* s_value = s_attn;            // 24x64 (overwrites dead attn)

    for (int idx = tid; idx < Tdim * Ddim; idx += 256)
        s_gcn[idx] = g_gcn[(size_t)(b * Ndim + n) * Tdim * Ddim + idx];

    // ---- value = lrelu(val @ out_w + out_b) ----
    float4 valacc[2];
    {
        int nt = 0;
        for (int task = tid; task < 384; task += 256, ++nt) {
            int t = task >> 4, e4 = task & 15;
            float4 a = *(const float4*)&out_b[e4 * 4];
            #pragma unroll 4
            for (int i = 0; i < 128; ++i) {
                float xv = s_val[t * 128 + i];
                float4 w = *(const float4*)&out_w[i * 64 + e4 * 4];
                a.x += xv * w.x; a.y += xv * w.y; a.z += xv * w.z; a.w += xv * w.w;
            }
            valacc[nt] = make_float4(lrelu(a.x), lrelu(a.y), lrelu(a.z), lrelu(a.w));
        }
    }
    __syncthreads();   // s_attn fully read (stage C) before overwrite as s_value
    {
        int nt = 0;
        for (int task = tid; task < 384; task += 256, ++nt) {
            int t = task >> 4, e4 = task & 15;
            *(float4*)&s_value[t * 64 + e4 * 4] = valacc[nt];
        }
    }
    __syncthreads();

    // ---- gate + final ----
    for (int task = tid; task < 384; task += 256) {
        int t = task >> 4, e4 = task & 15;
        float4 a = *(const float4*)&gate_b[e4 * 4];
        #pragma unroll 4
        for (int i = 0; i < 64; ++i) {
            float gv = s_gcn[t * 64 + i];
            float4 w = *(const float4*)&gate_w[i * 64 + e4 * 4];
            a.x += gv * w.x; a.y += gv * w.y; a.z += gv * w.z; a.w += gv * w.w;
        }
        #pragma unroll 4
        for (int i = 0; i < 64; ++i) {
            float vv = s_value[t * 64 + i];
            float4 w = *(const float4*)&gate_w[(64 + i) * 64 + e4 * 4];
            a.x += vv * w.x; a.y += vv * w.y; a.z += vv * w.z; a.w += vv * w.w;
        }
        float4 z = make_float4(1.f / (1.f + expf(-a.x)), 1.f / (1.f + expf(-a.y)),
                               1.f / (1.f + expf(-a.z)), 1.f / (1.f + expf(-a.w)));
        float4 g  = *(const float4*)&s_gcn[t * 64 + e4 * 4];
        float4 vv = *(const float4*)&s_value[t * 64 + e4 * 4];
        size_t ho = ((size_t)(b * Ndim + n) * Tdim + t) * Ddim + e4 * 4;
        float4 h4 = *(const float4*)&hidden[ho];
        float4 o;
        o.x = z.x * g.x + (1.f - z.x) * vv.x + h4.x;
        o.y = z.y * g.y + (1.f - z.y) * vv.y + h4.y;
        o.z = z.z * g.z + (1.f - z.z) * vv.z + h4.z;
        o.w = z.w * g.w + (1.f - z.w) * vv.w + h4.w;
        *(float4*)&out[ho] = o;
    }
}

// ============================================================================
extern "C" void kernel_launch(void* const* d_in, const int* in_sizes, int n_in,
                              void* d_out, int out_size) {
    (void)in_sizes; (void)n_in; (void)out_size;
    const float* hidden   = (const float*)d_in[0];
    const float* tXin     = (const float*)d_in[1];
    const float* matrix   = (const float*)d_in[2];
    const float* gcn_w    = (const float*)d_in[3];
    const float* gcn_b    = (const float*)d_in[4];
    const float* node_emb = (const float*)d_in[5];
    const float* tproj_w  = (const float*)d_in[6];
    const float* tproj_b  = (const float*)d_in[7];
    const float* WK       = (const float*)d_in[8];
    const float* WQ       = (const float*)d_in[9];
    const float* WV       = (const float*)d_in[10];
    const float* out_w    = (const float*)d_in[11];
    const float* out_b    = (const float*)d_in[12];
    const float* gate_w   = (const float*)d_in[13];
    const float* gate_b   = (const float*)d_in[14];
    float* out = (float*)d_out;

    k_tfeat<<<1, 512>>>(tXin, tproj_w, tproj_b);
    k_support_gcn<<<dim3(6, 24, 8), 256>>>(matrix, hidden, gcn_w, gcn_b);
    k_buildW<<<dim3(16, 8, 3), 256>>>(WQ, WK, WV, node_emb);
    k_qkvproj<<<dim3(325, 8, 3), 256>>>(hidden, tXin);
    k_attn<<<dim3(325, 8), 256>>>(hidden, out_w, out_b, gate_w, gate_b, out);
}

// round 3
// speedup vs baseline: 1.1176x; 1.1176x over previous
#include <cuda_runtime.h>
#include <cuda_fp16.h>
#include <math.h>

#define Bdim 8
#define Ndim 325
#define Tdim 24
#define Ddim 64
#define Hh   8
#define Mm   16
#define E2d  128

// ---------------- scratch (device globals; no runtime allocation) ----------------
__device__ float  g_tfeat[Bdim * Mm];                                   // (B,16)
__device__ float  g_gcn[(size_t)Bdim * Ndim * Tdim * Ddim];             // 16 MB
__device__ __half g_W[(size_t)3 * Bdim * Ndim * E2d * E2d];             // 255 MB (fp16)
__device__ float  g_qkv[(size_t)3 * Bdim * Ndim * Tdim * E2d];          // 96 MB

__device__ __forceinline__ float lrelu(float x) { return x >= 0.f ? x : 0.1f * x; }

// ============================================================================
// K0: tfeat[b,m] = tanh( mean_t(tXin[b,0,t,:]) @ tproj_w + tproj_b )
// ============================================================================
__global__ void k_tfeat(const float* __restrict__ tXin,
                        const float* __restrict__ tproj_w,
                        const float* __restrict__ tproj_b) {
    __shared__ float s_mean[Bdim * Ddim];
    int tid = threadIdx.x;
    if (tid < Bdim * Ddim) {
        int b = tid >> 6, d = tid & 63;
        float s = 0.f;
        #pragma unroll
        for (int t = 0; t < Tdim; ++t)
            s += tXin[((size_t)(b * Ndim) * Tdim + t) * Ddim + d];
        s_mean[tid] = s * (1.0f / Tdim);
    }
    __syncthreads();
    if (tid < Bdim * Mm) {
        int b = tid >> 4, m = tid & 15;
        float a = tproj_b[m];
        #pragma unroll
        for (int d = 0; d < Ddim; ++d)
            a += s_mean[b * Ddim + d] * tproj_w[d * Mm + m];
        g_tfeat[tid] = tanhf(a);
    }
}

// ============================================================================
// K1: support[b,n,t,d] = sum_m matrix[b,t,n,m] * hidden[b,m,t,d]
//     gcn_out = relu(support @ gcn_w + gcn_b)   (fused epilogue)
// grid (ceil(N/64), T, B), block 256
// ============================================================================
__global__ void k_support_gcn(const float* __restrict__ matrix,
                              const float* __restrict__ hidden,
                              const float* __restrict__ gcn_w,
                              const float* __restrict__ gcn_b) {
    __shared__ float smem[8448];              // 33.8 KB
    float* s_hid = smem;                      // [32][64]
    float* s_mat = smem + 2048;               // [64][33]
    const int tid = threadIdx.x;
    const int n0 = blockIdx.x * 64;
    const int t  = blockIdx.y;
    const int b  = blockIdx.z;
    const int tx = tid & 15;                  // d-quad
    const int ty = tid >> 4;                  // row slot 0..15
    float4 acc[4];
    #pragma unroll
    for (int j = 0; j < 4; ++j) acc[j] = make_float4(0.f, 0.f, 0.f, 0.f);

    for (int mc = 0; mc < 11; ++mc) {
        const int m0 = mc * 32;
        for (int idx = tid; idx < 2048; idx += 256) {
            int mm = idx >> 6, d = idx & 63;
            int m = m0 + mm;
            s_hid[idx] = (m < Ndim) ? hidden[((size_t)(b * Ndim + m) * Tdim + t) * Ddim + d] : 0.f;
        }
        for (int idx = tid; idx < 2048; idx += 256) {
            int r = idx >> 5, mm = idx & 31;
            int n = n0 + r, m = m0 + mm;
            s_mat[r * 33 + mm] = (n < Ndim && m < Ndim)
                ? matrix[((size_t)(b * Tdim + t) * Ndim + n) * Ndim + m] : 0.f;
        }
        __syncthreads();
        #pragma unroll 8
        for (int mm = 0; mm < 32; ++mm) {
            float4 h4 = *(const float4*)&s_hid[mm * 64 + tx * 4];
            #pragma unroll
            for (int j = 0; j < 4; ++j) {
                float mv = s_mat[(ty + 16 * j) * 33 + mm];
                acc[j].x += mv * h4.x; acc[j].y += mv * h4.y;
                acc[j].z += mv * h4.z; acc[j].w += mv * h4.w;
            }
        }
        __syncthreads();
    }

    // ---- stage 2: gcn ----
    float* s_sup = smem;                      // [64][68]
    float* s_gw  = smem + 4352;               // [64][64]
    #pragma unroll
    for (int j = 0; j < 4; ++j)
        *(float4*)&s_sup[(ty + 16 * j) * 68 + tx * 4] = acc[j];
    for (int idx = tid; idx < 4096; idx += 256) s_gw[idx] = gcn_w[idx];
    __syncthreads();

    for (int task = tid; task < 1024; task += 256) {
        int r = task >> 4, e4 = task & 15;
        int n = n0 + r;
        if (n >= Ndim) continue;
        float4 a = *(const float4*)&gcn_b[e4 * 4];
        #pragma unroll 4
        for (int d = 0; d < 64; ++d) {
            float sv = s_sup[r * 68 + d];
            float4 g = *(const float4*)&s_gw[d * 64 + e4 * 4];
            a.x += sv * g.x; a.y += sv * g.y; a.z += sv * g.z; a.w += sv * g.w;
        }
        a.x = fmaxf(a.x, 0.f); a.y = fmaxf(a.y, 0.f);
        a.z = fmaxf(a.z, 0.f); a.w = fmaxf(a.w, 0.f);
        *(float4*)&g_gcn[((size_t)(b * Ndim + n) * Tdim + t) * Ddim + e4 * 4] = a;
    }
}

// ============================================================================
// K2: materialize W[mat,b,n,i,k] = sum_m node_emb[n,m]*tfeat[b,m]*Wmat[m,i,k]
// OUTPUT IN FP16. grid (16, B, 3), block 256. Each thread: fixed (i, k-quad),
// sweeps all n. Each WQ/WK/WV element is read exactly once per b.
// ============================================================================
__global__ void k_buildW(const float* __restrict__ wq,
                         const float* __restrict__ wk,
                         const float* __restrict__ wv,
                         const float* __restrict__ node_emb) {
    __shared__ float s_ne[Ndim * Mm];         // 5200 floats = 20.8 KB
    const int tid  = threadIdx.x;
    const int k4   = tid & 31;
    const int iloc = tid >> 5;
    const int i    = blockIdx.x * 8 + iloc;
    const int b    = blockIdx.y;
    const int mat  = blockIdx.z;
    const float* Wsel = (mat == 0) ? wq : (mat == 1) ? wk : wv;

    for (int idx = tid; idx < Ndim * Mm; idx += 256) s_ne[idx] = node_emb[idx];

    float4 v[16];
    #pragma unroll
    for (int m = 0; m < 16; ++m) {
        float4 w = *(const float4*)&Wsel[(size_t)m * 16384 + i * 128 + k4 * 4];
        float tf = g_tfeat[b * 16 + m];
        v[m] = make_float4(w.x * tf, w.y * tf, w.z * tf, w.w * tf);
    }
    __syncthreads();

    __half* outp = &g_W[((size_t)(mat * Bdim + b) * Ndim) * 16384 + i * 128 + k4 * 4];
    for (int n = 0; n < Ndim; ++n) {
        float4 o = make_float4(0.f, 0.f, 0.f, 0.f);
        const float* ne = &s_ne[n * 16];
        #pragma unroll
        for (int m = 0; m < 16; ++m) {
            float c = ne[m];
            o.x += c * v[m].x; o.y += c * v[m].y;
            o.z += c * v[m].z; o.w += c * v[m].w;
        }
        __half2 h01 = __floats2half2_rn(o.x, o.y);
        __half2 h23 = __floats2half2_rn(o.z, o.w);
        uint2 packed = make_uint2(*(unsigned*)&h01, *(unsigned*)&h23);
        *(uint2*)(outp + (size_t)n * 16384) = packed;
    }
}

// ============================================================================
// K3: q/k/v[b,n,t,k] = lrelu( sum_i qkv[b,n,t,i] * W[mat,b,n,i,k] )
// W in fp16; fp32 accumulate. unroll 8 for MLP. grid (N, B, 3), block 256.
// ============================================================================
__global__ void k_qkvproj(const float* __restrict__ hidden,
                          const float* __restrict__ tXin) {
    __shared__ float s_x[Tdim * E2d];         // 3072 floats = 12 KB
    const int tid = threadIdx.x;
    const int n = blockIdx.x, b = blockIdx.y, mat = blockIdx.z;

    for (int idx = tid; idx < Tdim * E2d; idx += 256) {
        int t = idx >> 7, i = idx & 127;
        s_x[idx] = (i < 64)
            ? hidden[((size_t)(b * Ndim + n) * Tdim + t) * Ddim + i]
            : tXin  [((size_t)(b * Ndim + n) * Tdim + t) * Ddim + (i - 64)];
    }
    __syncthreads();

    const int k4 = tid & 31, slot = tid >> 5;
    const int t0 = slot * 3;
    const __half* wp = &g_W[((size_t)(mat * Bdim + b) * Ndim + n) * 16384 + k4 * 4];
    float4 a0 = make_float4(0.f,0.f,0.f,0.f), a1 = a0, a2 = a0;
    #pragma unroll 8
    for (int i = 0; i < 128; ++i) {
        uint2 raw = *(const uint2*)(wp + (size_t)i * 128);
        float2 w01 = __half22float2(*(const __half2*)&raw.x);
        float2 w23 = __half22float2(*(const __half2*)&raw.y);
        float x0 = s_x[t0 * 128 + i];
        float x1 = s_x[(t0 + 1) * 128 + i];
        float x2 = s_x[(t0 + 2) * 128 + i];
        a0.x += x0 * w01.x; a0.y += x0 * w01.y; a0.z += x0 * w23.x; a0.w += x0 * w23.y;
        a1.x += x1 * w01.x; a1.y += x1 * w01.y; a1.z += x1 * w23.x; a1.w += x1 * w23.y;
        a2.x += x2 * w01.x; a2.y += x2 * w01.y; a2.z += x2 * w23.x; a2.w += x2 * w23.y;
    }
    const size_t qbase = ((size_t)mat * (Bdim * Ndim) * Tdim + (size_t)(b * Ndim + n) * Tdim) * E2d;
    float4 r;
    r = make_float4(lrelu(a0.x), lrelu(a0.y), lrelu(a0.z), lrelu(a0.w));
    *(float4*)&g_qkv[qbase + (size_t)t0 * 128 + k4 * 4] = r;
    r = make_float4(lrelu(a1.x), lrelu(a1.y), lrelu(a1.z), lrelu(a1.w));
    *(float4*)&g_qkv[qbase + (size_t)(t0 + 1) * 128 + k4 * 4] = r;
    r = make_float4(lrelu(a2.x), lrelu(a2.y), lrelu(a2.z), lrelu(a2.w));
    *(float4*)&g_qkv[qbase + (size_t)(t0 + 2) * 128 + k4 * 4] = r;
}

// ============================================================================
// K4: per-(b,n): causal attention + out-proj + gate + residual
// grid (N, B), block 256, STATIC smem 43 KB
// ============================================================================
__global__ void k_attn(const float* __restrict__ hidden,
                       const float* __restrict__ out_w,
                       const float* __restrict__ out_b,
                       const float* __restrict__ gate_w,
                       const float* __restrict__ gate_b,
                       float* __restrict__ out) {
    __shared__ float sm[10752];         // 43008 bytes
    float* s_k    = sm;                 // 3072 (later: val 24x128)
    float* s_v    = sm + 3072;          // 3072 (later: gcn 24x64)
    float* s_attn = sm + 6144;          // 4608 (later: value 24x64)
    const int tid = threadIdx.x;
    const int n = blockIdx.x, b = blockIdx.y;
    const size_t qstride = (size_t)Bdim * Ndim * Tdim * E2d;
    const size_t base    = (size_t)(b * Ndim + n) * Tdim * E2d;

    for (int idx = tid; idx < Tdim * E2d; idx += 256) {
        s_k[idx] = g_qkv[qstride + base + idx];
        s_v[idx] = g_qkv[2 * qstride + base + idx];
    }
    __syncthreads();

    // ---- scores + causal softmax: one thread per (t,h); q straight from global ----
    if (tid < 192) {
        int t = tid >> 3, h = tid & 7;
        float qreg[16];
        #pragma unroll
        for (int e = 0; e < 16; ++e) qreg[e] = g_qkv[base + t * 128 + h * 16 + e];
        float* arow = &s_attn[(h * 24 + t) * 24];
        float mx = -1e30f;
        for (int s = 0; s <= t; ++s) {
            float d = 0.f;
            #pragma unroll
            for (int e = 0; e < 16; ++e) d += qreg[e] * s_k[s * 128 + h * 16 + e];
            d *= 0.25f;                          // 1/sqrt(16)
            arow[s] = d;
            mx = fmaxf(mx, d);
        }
        float sum = 0.f;
        for (int s = 0; s <= t; ++s) { float e_ = expf(arow[s] - mx); arow[s] = e_; sum += e_; }
        float inv = 1.f / sum;
        for (int s = 0; s < 24; ++s) arow[s] = (s <= t) ? arow[s] * inv : 0.f;
    }
    __syncthreads();

    // ---- val[t,k] = sum_s attn[h,t,s]*v[s,k]  (h = k/16); write into s_k region ----
    {
        const int k4 = tid & 31, slot = tid >> 5;
        const int h = k4 >> 2;
        float4 acc[3];
        #pragma unroll
        for (int j = 0; j < 3; ++j) acc[j] = make_float4(0.f, 0.f, 0.f, 0.f);
        for (int s = 0; s < 24; ++s) {
            float4 v4 = *(const float4*)&s_v[s * 128 + k4 * 4];
            #pragma unroll
            for (int j = 0; j < 3; ++j) {
                float a = s_attn[(h * 24 + (slot * 3 + j)) * 24 + s];
                acc[j].x += a * v4.x; acc[j].y += a * v4.y;
                acc[j].z += a * v4.z; acc[j].w += a * v4.w;
            }
        }
        __syncthreads();   // everyone done reading s_k (as k) before overwrite
        #pragma unroll
        for (int j = 0; j < 3; ++j)
            *(float4*)&s_k[(slot * 3 + j) * 128 + k4 * 4] = acc[j];
    }
    __syncthreads();

    float* s_val   = s_k;               // 24x128
    float* s_gcn   = s_v;               // 24x64 (overwrites dead v)
    float* s_value = s_attn;            // 24x64 (overwrites dead attn)

    for (int idx = tid; idx < Tdim * Ddim; idx += 256)
        s_gcn[idx] = g_gcn[(size_t)(b * Ndim + n) * Tdim * Ddim + idx];

    // ---- value = lrelu(val @ out_w + out_b) ----
    float4 valacc[2];
    {
        int nt = 0;
        for (int task = tid; task < 384; task += 256, ++nt) {
            int t = task >> 4, e4 = task & 15;
            float4 a = *(const float4*)&out_b[e4 * 4];
            #pragma unroll 4
            for (int i = 0; i < 128; ++i) {
                float xv = s_val[t * 128 + i];
                float4 w = *(const float4*)&out_w[i * 64 + e4 * 4];
                a.x += xv * w.x; a.y += xv * w.y; a.z += xv * w.z; a.w += xv * w.w;
            }
            valacc[nt] = make_float4(lrelu(a.x), lrelu(a.y), lrelu(a.z), lrelu(a.w));
        }
    }
    __syncthreads();   // s_attn fully read before overwrite as s_value
    {
        int nt = 0;
        for (int task = tid; task < 384; task += 256, ++nt) {
            int t = task >> 4, e4 = task & 15;
            *(float4*)&s_value[t * 64 + e4 * 4] = valacc[nt];
        }
    }
    __syncthreads();

    // ---- gate + final ----
    for (int task = tid; task < 384; task += 256) {
        int t = task >> 4, e4 = task & 15;
        float4 a = *(const float4*)&gate_b[e4 * 4];
        #pragma unroll 4
        for (int i = 0; i < 64; ++i) {
            float gv = s_gcn[t * 64 + i];
            float4 w = *(const float4*)&gate_w[i * 64 + e4 * 4];
            a.x += gv * w.x; a.y += gv * w.y; a.z += gv * w.z; a.w += gv * w.w;
        }
        #pragma unroll 4
        for (int i = 0; i < 64; ++i) {
            float vv = s_value[t * 64 + i];
            float4 w = *(const float4*)&gate_w[(64 + i) * 64 + e4 * 4];
            a.x += vv * w.x; a.y += vv * w.y; a.z += vv * w.z; a.w += vv * w.w;
        }
        float4 z = make_float4(1.f / (1.f + expf(-a.x)), 1.f / (1.f + expf(-a.y)),
                               1.f / (1.f + expf(-a.z)), 1.f / (1.f + expf(-a.w)));
        float4 g  = *(const float4*)&s_gcn[t * 64 + e4 * 4];
        float4 vv = *(const float4*)&s_value[t * 64 + e4 * 4];
        size_t ho = ((size_t)(b * Ndim + n) * Tdim + t) * Ddim + e4 * 4;
        float4 h4 = *(const float4*)&hidden[ho];
        float4 o;
        o.x = z.x * g.x + (1.f - z.x) * vv.x + h4.x;
        o.y = z.y * g.y + (1.f - z.y) * vv.y + h4.y;
        o.z = z.z * g.z + (1.f - z.z) * vv.z + h4.z;
        o.w = z.w * g.w + (1.f - z.w) * vv.w + h4.w;
        *(float4*)&out[ho] = o;
    }
}

// ============================================================================
extern "C" void kernel_launch(void* const* d_in, const int* in_sizes, int n_in,
                              void* d_out, int out_size) {
    (void)in_sizes; (void)n_in; (void)out_size;
    const float* hidden   = (const float*)d_in[0];
    const float* tXin     = (const float*)d_in[1];
    const float* matrix   = (const float*)d_in[2];
    const float* gcn_w    = (const float*)d_in[3];
    const float* gcn_b    = (const float*)d_in[4];
    const float* node_emb = (const float*)d_in[5];
    const float* tproj_w  = (const float*)d_in[6];
    const float* tproj_b  = (const float*)d_in[7];
    const float* WK       = (const float*)d_in[8];
    const float* WQ       = (const float*)d_in[9];
    const float* WV       = (const float*)d_in[10];
    const float* out_w    = (const float*)d_in[11];
    const float* out_b    = (const float*)d_in[12];
    const float* gate_w   = (const float*)d_in[13];
    const float* gate_b   = (const float*)d_in[14];
    float* out = (float*)d_out;

    k_tfeat<<<1, 512>>>(tXin, tproj_w, tproj_b);
    k_support_gcn<<<dim3(6, 24, 8), 256>>>(matrix, hidden, gcn_w, gcn_b);
    k_buildW<<<dim3(16, 8, 3), 256>>>(WQ, WK, WV, node_emb);
    k_qkvproj<<<dim3(325, 8, 3), 256>>>(hidden, tXin);
    k_attn<<<dim3(325, 8), 256>>>(hidden, out_w, out_b, gate_w, gate_b, out);
}